// round 4
// baseline (speedup 1.0000x reference)
#include <cuda_runtime.h>
#include <math.h>

#define D 128
#define MAX_N 50000

// ---------------- scratch (static device allocations; no runtime alloc) ---------
__device__ float g_agg_rates[MAX_N * D];   // dst = item
__device__ float g_agg_rev[MAX_N * D];     // dst = user
__device__ float g_agg_fol[MAX_N * D];     // dst = user
__device__ float g_cnt_rates[MAX_N];
__device__ float g_cnt_rev[MAX_N];
__device__ float g_cnt_fol[MAX_N];
__device__ float g_wc_user[384 * D];       // [K=384][J=128] combined weights (user)
__device__ float g_wc_item[256 * D];       // [K=256][J=128] combined weights (item)
__device__ float g_bias_user[D];
__device__ float g_bias_item[D];

// ---------------- zero scratch ---------------------------------------------------
__global__ void zero_kernel(int n_user, int n_item) {
    size_t i = (size_t)blockIdx.x * blockDim.x + threadIdx.x;
    size_t stride = (size_t)gridDim.x * blockDim.x;
    size_t nI4 = (size_t)n_item * D / 4;
    size_t nU4 = (size_t)n_user * D / 4;
    float4 z = make_float4(0.f, 0.f, 0.f, 0.f);
    for (size_t k = i; k < nI4; k += stride) ((float4*)g_agg_rates)[k] = z;
    for (size_t k = i; k < nU4; k += stride) ((float4*)g_agg_rev)[k] = z;
    for (size_t k = i; k < nU4; k += stride) ((float4*)g_agg_fol)[k] = z;
    for (size_t k = i; k < (size_t)n_item; k += stride) g_cnt_rates[k] = 0.f;
    for (size_t k = i; k < (size_t)n_user; k += stride) g_cnt_rev[k] = 0.f;
    for (size_t k = i; k < (size_t)n_user; k += stride) g_cnt_fol[k] = 0.f;
}

// ---------------- edge scatter: agg[dst] += x_src[src], cnt[dst] += 1 ------------
// one warp per edge; 32 lanes x float4 = 128 floats; 16B vector atomics
__global__ void scatter_kernel(const int* __restrict__ ei,
                               const float* __restrict__ xsrc,
                               int rel, int E) {
    int w = (int)(((size_t)blockIdx.x * blockDim.x + threadIdx.x) >> 5);
    int lane = threadIdx.x & 31;
    if (w >= E) return;

    float* agg = (rel == 0) ? g_agg_rates : (rel == 1) ? g_agg_rev : g_agg_fol;
    float* cnt = (rel == 0) ? g_cnt_rates : (rel == 1) ? g_cnt_rev : g_cnt_fol;

    int src = __ldg(ei + w);
    int dst = __ldg(ei + E + w);

    float4 v = *(const float4*)(xsrc + (size_t)src * D + lane * 4);
    float* p = agg + (size_t)dst * D + lane * 4;
    asm volatile("red.global.add.v4.f32 [%0], {%1, %2, %3, %4};"
                 :: "l"(p), "f"(v.x), "f"(v.y), "f"(v.z), "f"(v.w)
                 : "memory");
    if (lane == 0) atomicAdd(cnt + dst, 1.0f);
}

// ---------------- combined-weight prep -------------------------------------------
// out_user = 0.5*(mean_rev@Wl_rev^T + bl_rev + x_u@Wr_rev^T
//               + mean_fol@Wl_fol^T + bl_fol + x_u@Wr_fol^T)
//          = [mean_rev | mean_fol | x_u] @ Wc_user + bias_user
__global__ void build_user_wc(const float* __restrict__ Wl_rev, const float* __restrict__ bl_rev,
                              const float* __restrict__ Wr_rev,
                              const float* __restrict__ Wl_fol, const float* __restrict__ bl_fol,
                              const float* __restrict__ Wr_fol) {
    int t = blockIdx.x * blockDim.x + threadIdx.x;
    if (t < 384 * D) {
        int k = t >> 7, j = t & 127;
        float v;
        if (k < 128)       v = 0.5f * Wl_rev[j * D + k];
        else if (k < 256)  v = 0.5f * Wl_fol[j * D + (k - 128)];
        else               v = 0.5f * (Wr_rev[j * D + (k - 256)] + Wr_fol[j * D + (k - 256)]);
        g_wc_user[t] = v;
    }
    if (t < D) g_bias_user[t] = 0.5f * (bl_rev[t] + bl_fol[t]);
}

// out_item = [mean_rates | x_item] @ Wc_item + bl_rates
__global__ void build_item_wc(const float* __restrict__ Wl, const float* __restrict__ bl,
                              const float* __restrict__ Wr) {
    int t = blockIdx.x * blockDim.x + threadIdx.x;
    if (t < 256 * D) {
        int k = t >> 7, j = t & 127;
        float v = (k < 128) ? Wl[j * D + k] : Wr[j * D + (k - 128)];
        g_wc_item[t] = v;
    }
    if (t < D) g_bias_item[t] = bl[t];
}

// ---------------- fused mean + dual-linear GEMM ----------------------------------
// gridDim.y selects node type: 0 = user (K=384, 3 chunks), 1 = item (K=256, 2 chunks)
// Block: 128 rows x 128 cols, 256 threads, 8x8 register tiles.
__global__ __launch_bounds__(256, 2)
void gemm_fused(const float* __restrict__ x_user, const float* __restrict__ x_item,
                float* __restrict__ out_user, float* __restrict__ out_item,
                int n_user, int n_item) {
    __shared__ float As[32][132];   // [k][row] transposed
    __shared__ float Bs[32][132];   // [k][j]
    __shared__ float inv_s[128];

    const int mode = blockIdx.y;    // 0 user, 1 item
    const int nrows   = (mode == 0) ? n_user : n_item;
    const int nchunks = (mode == 0) ? 3 : 2;
    const float* Wc   = (mode == 0) ? g_wc_user : g_wc_item;
    const float* bias = (mode == 0) ? g_bias_user : g_bias_item;
    float* out        = (mode == 0) ? out_user : out_item;

    const int tid = threadIdx.x;
    const int tx = tid & 15;    // row-group
    const int ty = tid >> 4;    // col-group
    const int row0 = blockIdx.x * 128;
    if (row0 >= nrows) return;

    float acc[8][8];
#pragma unroll
    for (int i = 0; i < 8; i++)
#pragma unroll
        for (int j = 0; j < 8; j++) acc[i][j] = 0.f;

    for (int c = 0; c < nchunks; c++) {
        const float* A;
        const float* C;
        if (mode == 0) {
            if (c == 0)      { A = g_agg_rev; C = g_cnt_rev; }
            else if (c == 1) { A = g_agg_fol; C = g_cnt_fol; }
            else             { A = x_user;    C = nullptr;   }
        } else {
            if (c == 0)      { A = g_agg_rates; C = g_cnt_rates; }
            else             { A = x_item;      C = nullptr;     }
        }

        __syncthreads();   // everyone done with previous tiles / inv_s
        if (tid < 128) {
            int r = row0 + tid;
            float iv = 1.0f;
            if (C != nullptr) {
                float cv = (r < nrows) ? C[r] : 1.0f;
                iv = 1.0f / fmaxf(cv, 1.0f);
            }
            inv_s[tid] = iv;
        }

#pragma unroll 1
        for (int ks = 0; ks < 4; ks++) {
            __syncthreads();
            // load A subtile (128 rows x 32 k), scaled by 1/cnt, stored transposed
#pragma unroll
            for (int p = 0; p < 4; p++) {
                int r = p * 32 + (tid >> 3);
                int kk = (tid & 7) << 2;
                int grow = row0 + r;
                float4 v = make_float4(0.f, 0.f, 0.f, 0.f);
                if (grow < nrows)
                    v = *(const float4*)(A + (size_t)grow * D + (ks << 5) + kk);
                float iv = inv_s[r];
                As[kk + 0][r] = v.x * iv;
                As[kk + 1][r] = v.y * iv;
                As[kk + 2][r] = v.z * iv;
                As[kk + 3][r] = v.w * iv;
            }
            // load B subtile (32 k x 128 j)
            {
                int k = tid >> 3;
                int j0 = (tid & 7) << 2;
                int kb = (c << 7) + (ks << 5) + k;
#pragma unroll
                for (int p = 0; p < 4; p++) {
                    float4 v = *(const float4*)(Wc + (size_t)kb * D + p * 32 + j0);
                    *(float4*)&Bs[k][p * 32 + j0] = v;
                }
            }
            __syncthreads();
            // 8x8 outer-product accumulation over 32 k
#pragma unroll
            for (int k = 0; k < 32; k++) {
                float a[8], b[8];
                *(float4*)&a[0] = *(const float4*)&As[k][tx * 8];
                *(float4*)&a[4] = *(const float4*)&As[k][tx * 8 + 4];
                *(float4*)&b[0] = *(const float4*)&Bs[k][ty * 8];
                *(float4*)&b[4] = *(const float4*)&Bs[k][ty * 8 + 4];
#pragma unroll
                for (int i = 0; i < 8; i++)
#pragma unroll
                    for (int j = 0; j < 8; j++)
                        acc[i][j] += a[i] * b[j];
            }
        }
    }

    // epilogue: + bias, write out
    float bv[8];
    *(float4*)&bv[0] = *(const float4*)&bias[ty * 8];
    *(float4*)&bv[4] = *(const float4*)&bias[ty * 8 + 4];
#pragma unroll
    for (int i = 0; i < 8; i++) {
        int r = row0 + tx * 8 + i;
        if (r < nrows) {
            float4 o0 = make_float4(acc[i][0] + bv[0], acc[i][1] + bv[1],
                                    acc[i][2] + bv[2], acc[i][3] + bv[3]);
            float4 o1 = make_float4(acc[i][4] + bv[4], acc[i][5] + bv[5],
                                    acc[i][6] + bv[6], acc[i][7] + bv[7]);
            *(float4*)(out + (size_t)r * D + ty * 8)     = o0;
            *(float4*)(out + (size_t)r * D + ty * 8 + 4) = o1;
        }
    }
}

// ---------------- launch ---------------------------------------------------------
extern "C" void kernel_launch(void* const* d_in, const int* in_sizes, int n_in,
                              void* d_out, int out_size) {
    const float* x_user   = (const float*)d_in[0];
    const float* x_item   = (const float*)d_in[1];
    const int*   ei_rates = (const int*)d_in[2];
    const int*   ei_rev   = (const int*)d_in[3];
    const int*   ei_fol   = (const int*)d_in[4];
    const float* Wl_rates = (const float*)d_in[5];
    const float* bl_rates = (const float*)d_in[6];
    const float* Wr_rates = (const float*)d_in[7];
    const float* Wl_rev   = (const float*)d_in[8];
    const float* bl_rev   = (const float*)d_in[9];
    const float* Wr_rev   = (const float*)d_in[10];
    const float* Wl_fol   = (const float*)d_in[11];
    const float* bl_fol   = (const float*)d_in[12];
    const float* Wr_fol   = (const float*)d_in[13];

    const int n_user = in_sizes[0] / D;
    const int n_item = in_sizes[1] / D;
    const int E      = in_sizes[2] / 2;

    float* out_user = (float*)d_out;
    float* out_item = out_user + (size_t)n_user * D;

    // 1) zero scratch
    zero_kernel<<<4096, 256>>>(n_user, n_item);

    // 2) build combined weights/biases (independent, tiny)
    build_user_wc<<<(384 * D + 255) / 256, 256>>>(Wl_rev, bl_rev, Wr_rev,
                                                  Wl_fol, bl_fol, Wr_fol);
    build_item_wc<<<(256 * D + 255) / 256, 256>>>(Wl_rates, bl_rates, Wr_rates);

    // 3) edge scatter (one warp per edge)
    {
        long long thr = (long long)E * 32;
        int blocks = (int)((thr + 255) / 256);
        scatter_kernel<<<blocks, 256>>>(ei_rates, x_user, 0, E);  // user -> item
        scatter_kernel<<<blocks, 256>>>(ei_rev,   x_item, 1, E);  // item -> user
        scatter_kernel<<<blocks, 256>>>(ei_fol,   x_user, 2, E);  // user -> user
    }

    // 4) fused mean + GEMM + bias for both node types in one launch
    {
        int max_rows = (n_user > n_item) ? n_user : n_item;
        dim3 grid((max_rows + 127) / 128, 2);
        gemm_fused<<<grid, 256>>>(x_user, x_item, out_user, out_item, n_user, n_item);
    }
}

// round 6
// speedup vs baseline: 1.2240x; 1.2240x over previous
#include <cuda_runtime.h>
#include <math.h>

#define D 128
#define MAX_N 50000
#define MAX_E 600000
#define NPAD 50048

// ---------------- scratch (static device allocations; no runtime alloc) ---------
__device__ float g_mean_rates[MAX_N * D];   // dst = item
__device__ float g_mean_rev[MAX_N * D];     // dst = user
__device__ float g_mean_fol[MAX_N * D];     // dst = user
__device__ int   g_deg[3][NPAD];
__device__ int   g_ofs[3][NPAD + 1];
__device__ int   g_cur[3][NPAD];
__device__ int   g_esrc[3 * MAX_E];
__device__ float g_wc_user[384 * D];        // [K=384][J=128] combined weights (user)
__device__ float g_wc_item[256 * D];        // [K=256][J=128] combined weights (item)
__device__ float g_bias_user[D];
__device__ float g_bias_item[D];

// ---------------- zero degree counters -------------------------------------------
__global__ void zero_deg() {
    int i = blockIdx.x * blockDim.x + threadIdx.x;
    if (i < NPAD) {
        g_deg[0][i] = 0; g_deg[1][i] = 0; g_deg[2][i] = 0;
    }
}

// ---------------- degree histogram ------------------------------------------------
__global__ void hist_kernel(const int* __restrict__ ei0, const int* __restrict__ ei1,
                            const int* __restrict__ ei2, int E) {
    int rel = blockIdx.y;
    const int* ei = (rel == 0) ? ei0 : (rel == 1) ? ei1 : ei2;
    int e = blockIdx.x * blockDim.x + threadIdx.x;
    if (e < E) atomicAdd(&g_deg[rel][ei[E + e]], 1);
}

// ---------------- exclusive scan (one block per relation, shfl-based) ------------
__global__ void scan_kernel(int n0, int n1, int n2) {
    int rel = blockIdx.x;
    int n = (rel == 0) ? n0 : (rel == 1) ? n1 : n2;
    __shared__ int shw[32];
    int t = threadIdx.x;
    int lane = t & 31;
    int wid = t >> 5;
    int running = 0;
    for (int base = 0; base < n; base += 1024) {
        int idx = base + t;
        int v = (idx < n) ? g_deg[rel][idx] : 0;
        // inclusive warp scan
        int x = v;
#pragma unroll
        for (int off = 1; off < 32; off <<= 1) {
            int y = __shfl_up_sync(0xffffffffu, x, off);
            if (lane >= off) x += y;
        }
        if (lane == 31) shw[wid] = x;
        __syncthreads();
        if (wid == 0) {
            int s = shw[lane];
#pragma unroll
            for (int off = 1; off < 32; off <<= 1) {
                int y = __shfl_up_sync(0xffffffffu, s, off);
                if (lane >= off) s += y;
            }
            shw[lane] = s;
        }
        __syncthreads();
        int warpbase = (wid > 0) ? shw[wid - 1] : 0;
        int excl = running + warpbase + x - v;
        if (idx < n) {
            g_ofs[rel][idx] = excl;
            g_cur[rel][idx] = excl;
        }
        int total = shw[31];
        __syncthreads();
        running += total;
    }
    if (t == 0) g_ofs[rel][n] = running;
}

// ---------------- permute src ids into CSR order ---------------------------------
__global__ void permute_kernel(const int* __restrict__ ei0, const int* __restrict__ ei1,
                               const int* __restrict__ ei2, int E) {
    int rel = blockIdx.y;
    const int* ei = (rel == 0) ? ei0 : (rel == 1) ? ei1 : ei2;
    int e = blockIdx.x * blockDim.x + threadIdx.x;
    if (e < E) {
        int src = __ldg(ei + e);
        int dst = __ldg(ei + E + e);
        int pos = atomicAdd(&g_cur[rel][dst], 1);
        g_esrc[rel * MAX_E + pos] = src;
    }
}

// ---------------- atomic-free aggregation: mean over CSR neighborhoods -----------
// one warp per (rel, dst); 32 lanes x float4 = 128 floats; 4-way edge unroll
__global__ void aggregate_kernel(const float* __restrict__ x_user,
                                 const float* __restrict__ x_item,
                                 int n_user, int n_item) {
    int rel = blockIdx.y;
    int n = (rel == 0) ? n_item : n_user;
    const float* x = (rel == 1) ? x_item : x_user;
    float* mean = (rel == 0) ? g_mean_rates : (rel == 1) ? g_mean_rev : g_mean_fol;

    int w = (blockIdx.x * blockDim.x + threadIdx.x) >> 5;
    int lane = threadIdx.x & 31;
    if (w >= n) return;

    int start = g_ofs[rel][w];
    int end   = g_ofs[rel][w + 1];
    const int* esrc = g_esrc + rel * MAX_E;
    const size_t loff = (size_t)(lane * 4);

    float4 a0 = make_float4(0.f, 0.f, 0.f, 0.f);
    float4 a1 = make_float4(0.f, 0.f, 0.f, 0.f);
    float4 a2 = make_float4(0.f, 0.f, 0.f, 0.f);
    float4 a3 = make_float4(0.f, 0.f, 0.f, 0.f);
    int e = start;
    for (; e + 4 <= end; e += 4) {
        int s0 = __ldg(esrc + e);
        int s1 = __ldg(esrc + e + 1);
        int s2 = __ldg(esrc + e + 2);
        int s3 = __ldg(esrc + e + 3);
        float4 v0 = *(const float4*)(x + (size_t)s0 * D + loff);
        float4 v1 = *(const float4*)(x + (size_t)s1 * D + loff);
        float4 v2 = *(const float4*)(x + (size_t)s2 * D + loff);
        float4 v3 = *(const float4*)(x + (size_t)s3 * D + loff);
        a0.x += v0.x; a0.y += v0.y; a0.z += v0.z; a0.w += v0.w;
        a1.x += v1.x; a1.y += v1.y; a1.z += v1.z; a1.w += v1.w;
        a2.x += v2.x; a2.y += v2.y; a2.z += v2.z; a2.w += v2.w;
        a3.x += v3.x; a3.y += v3.y; a3.z += v3.z; a3.w += v3.w;
    }
    for (; e < end; e++) {
        int s0 = __ldg(esrc + e);
        float4 v0 = *(const float4*)(x + (size_t)s0 * D + loff);
        a0.x += v0.x; a0.y += v0.y; a0.z += v0.z; a0.w += v0.w;
    }
    int deg = end - start;
    float sc = (deg > 0) ? (1.0f / (float)deg) : 0.0f;
    float4 r;
    r.x = (a0.x + a1.x + a2.x + a3.x) * sc;
    r.y = (a0.y + a1.y + a2.y + a3.y) * sc;
    r.z = (a0.z + a1.z + a2.z + a3.z) * sc;
    r.w = (a0.w + a1.w + a2.w + a3.w) * sc;
    *(float4*)(mean + (size_t)w * D + loff) = r;
}

// ---------------- combined-weight prep -------------------------------------------
__global__ void build_user_wc(const float* __restrict__ Wl_rev, const float* __restrict__ bl_rev,
                              const float* __restrict__ Wr_rev,
                              const float* __restrict__ Wl_fol, const float* __restrict__ bl_fol,
                              const float* __restrict__ Wr_fol) {
    int t = blockIdx.x * blockDim.x + threadIdx.x;
    if (t < 384 * D) {
        int k = t >> 7, j = t & 127;
        float v;
        if (k < 128)       v = 0.5f * Wl_rev[j * D + k];
        else if (k < 256)  v = 0.5f * Wl_fol[j * D + (k - 128)];
        else               v = 0.5f * (Wr_rev[j * D + (k - 256)] + Wr_fol[j * D + (k - 256)]);
        g_wc_user[t] = v;
    }
    if (t < D) g_bias_user[t] = 0.5f * (bl_rev[t] + bl_fol[t]);
}

__global__ void build_item_wc(const float* __restrict__ Wl, const float* __restrict__ bl,
                              const float* __restrict__ Wr) {
    int t = blockIdx.x * blockDim.x + threadIdx.x;
    if (t < 256 * D) {
        int k = t >> 7, j = t & 127;
        float v = (k < 128) ? Wl[j * D + k] : Wr[j * D + (k - 128)];
        g_wc_item[t] = v;
    }
    if (t < D) g_bias_item[t] = bl[t];
}

// ---------------- fused dual-linear GEMM (means precomputed) ---------------------
// gridDim.y: 0 = user ([mean_rev|mean_fol|x_u]@Wc_user), 1 = item ([mean_rates|x_i]@Wc_item)
__global__ __launch_bounds__(256, 2)
void gemm_fused(const float* __restrict__ x_user, const float* __restrict__ x_item,
                float* __restrict__ out_user, float* __restrict__ out_item,
                int n_user, int n_item) {
    __shared__ float As[32][132];   // [k][row] transposed
    __shared__ float Bs[32][132];   // [k][j]

    const int mode = blockIdx.y;
    const int nrows   = (mode == 0) ? n_user : n_item;
    const int nchunks = (mode == 0) ? 3 : 2;
    const float* Wc   = (mode == 0) ? g_wc_user : g_wc_item;
    const float* bias = (mode == 0) ? g_bias_user : g_bias_item;
    float* out        = (mode == 0) ? out_user : out_item;

    const int tid = threadIdx.x;
    const int tx = tid & 15;
    const int ty = tid >> 4;
    const int row0 = blockIdx.x * 128;
    if (row0 >= nrows) return;

    float acc[8][8];
#pragma unroll
    for (int i = 0; i < 8; i++)
#pragma unroll
        for (int j = 0; j < 8; j++) acc[i][j] = 0.f;

    for (int c = 0; c < nchunks; c++) {
        const float* A;
        if (mode == 0) {
            A = (c == 0) ? g_mean_rev : (c == 1) ? g_mean_fol : x_user;
        } else {
            A = (c == 0) ? g_mean_rates : x_item;
        }

#pragma unroll 1
        for (int ks = 0; ks < 4; ks++) {
            __syncthreads();
            // load A subtile (128 rows x 32 k), stored transposed
#pragma unroll
            for (int p = 0; p < 4; p++) {
                int r = p * 32 + (tid >> 3);
                int kk = (tid & 7) << 2;
                int grow = row0 + r;
                float4 v = make_float4(0.f, 0.f, 0.f, 0.f);
                if (grow < nrows)
                    v = *(const float4*)(A + (size_t)grow * D + (ks << 5) + kk);
                As[kk + 0][r] = v.x;
                As[kk + 1][r] = v.y;
                As[kk + 2][r] = v.z;
                As[kk + 3][r] = v.w;
            }
            // load B subtile (32 k x 128 j)
            {
                int k = tid >> 3;
                int j0 = (tid & 7) << 2;
                int kb = (c << 7) + (ks << 5) + k;
#pragma unroll
                for (int p = 0; p < 4; p++) {
                    float4 v = *(const float4*)(Wc + (size_t)kb * D + p * 32 + j0);
                    *(float4*)&Bs[k][p * 32 + j0] = v;
                }
            }
            __syncthreads();
#pragma unroll
            for (int k = 0; k < 32; k++) {
                float a[8], b[8];
                *(float4*)&a[0] = *(const float4*)&As[k][tx * 8];
                *(float4*)&a[4] = *(const float4*)&As[k][tx * 8 + 4];
                *(float4*)&b[0] = *(const float4*)&Bs[k][ty * 8];
                *(float4*)&b[4] = *(const float4*)&Bs[k][ty * 8 + 4];
#pragma unroll
                for (int i = 0; i < 8; i++)
#pragma unroll
                    for (int j = 0; j < 8; j++)
                        acc[i][j] += a[i] * b[j];
            }
        }
    }

    float bv[8];
    *(float4*)&bv[0] = *(const float4*)&bias[ty * 8];
    *(float4*)&bv[4] = *(const float4*)&bias[ty * 8 + 4];
#pragma unroll
    for (int i = 0; i < 8; i++) {
        int r = row0 + tx * 8 + i;
        if (r < nrows) {
            float4 o0 = make_float4(acc[i][0] + bv[0], acc[i][1] + bv[1],
                                    acc[i][2] + bv[2], acc[i][3] + bv[3]);
            float4 o1 = make_float4(acc[i][4] + bv[4], acc[i][5] + bv[5],
                                    acc[i][6] + bv[6], acc[i][7] + bv[7]);
            *(float4*)(out + (size_t)r * D + ty * 8)     = o0;
            *(float4*)(out + (size_t)r * D + ty * 8 + 4) = o1;
        }
    }
}

// ---------------- launch ---------------------------------------------------------
extern "C" void kernel_launch(void* const* d_in, const int* in_sizes, int n_in,
                              void* d_out, int out_size) {
    const float* x_user   = (const float*)d_in[0];
    const float* x_item   = (const float*)d_in[1];
    const int*   ei_rates = (const int*)d_in[2];
    const int*   ei_rev   = (const int*)d_in[3];
    const int*   ei_fol   = (const int*)d_in[4];
    const float* Wl_rates = (const float*)d_in[5];
    const float* bl_rates = (const float*)d_in[6];
    const float* Wr_rates = (const float*)d_in[7];
    const float* Wl_rev   = (const float*)d_in[8];
    const float* bl_rev   = (const float*)d_in[9];
    const float* Wr_rev   = (const float*)d_in[10];
    const float* Wl_fol   = (const float*)d_in[11];
    const float* bl_fol   = (const float*)d_in[12];
    const float* Wr_fol   = (const float*)d_in[13];

    const int n_user = in_sizes[0] / D;
    const int n_item = in_sizes[1] / D;
    const int E      = in_sizes[2] / 2;

    float* out_user = (float*)d_out;
    float* out_item = out_user + (size_t)n_user * D;

    // 1) zero degree counters + weight prep (tiny)
    zero_deg<<<(NPAD + 255) / 256, 256>>>();
    build_user_wc<<<(384 * D + 255) / 256, 256>>>(Wl_rev, bl_rev, Wr_rev,
                                                  Wl_fol, bl_fol, Wr_fol);
    build_item_wc<<<(256 * D + 255) / 256, 256>>>(Wl_rates, bl_rates, Wr_rates);

    // 2) CSR build: histogram -> scan -> permute
    {
        dim3 grid((E + 255) / 256, 3);
        hist_kernel<<<grid, 256>>>(ei_rates, ei_rev, ei_fol, E);
        scan_kernel<<<3, 1024>>>(n_item, n_user, n_user);
        permute_kernel<<<grid, 256>>>(ei_rates, ei_rev, ei_fol, E);
    }

    // 3) atomic-free aggregation (mean) for all 3 relations in one launch
    {
        int max_n = (n_user > n_item) ? n_user : n_item;
        dim3 grid((max_n + 7) / 8, 3);
        aggregate_kernel<<<grid, 256>>>(x_user, x_item, n_user, n_item);
    }

    // 4) fused GEMM + bias for both node types in one launch
    {
        int max_rows = (n_user > n_item) ? n_user : n_item;
        dim3 grid((max_rows + 127) / 128, 2);
        gemm_fused<<<grid, 256>>>(x_user, x_item, out_user, out_item, n_user, n_item);
    }
}

// round 9
// speedup vs baseline: 1.2297x; 1.0046x over previous
#include <cuda_runtime.h>
#include <math.h>

#define D 128
#define MAX_N 50000
#define MAX_E 600000
#define NPAD 50048

// ---------------- scratch (static device allocations; no runtime alloc) ---------
__device__ float g_mean_rates[MAX_N * D];   // dst = item
__device__ float g_mean_rev[MAX_N * D];     // dst = user
__device__ float g_mean_fol[MAX_N * D];     // dst = user
__device__ int   g_deg[3][NPAD];
__device__ int   g_ofs[3][NPAD + 1];
__device__ int   g_cur[3][NPAD];
__device__ int   g_esrc[3 * MAX_E];
__device__ float g_wc_user[384 * D];        // [K=384][J=128] combined weights (user)
__device__ float g_wc_item[256 * D];        // [K=256][J=128] combined weights (item)
__device__ float g_bias_user[D];
__device__ float g_bias_item[D];

// ---------------- zero degree counters -------------------------------------------
__global__ void zero_deg() {
    int i = blockIdx.x * blockDim.x + threadIdx.x;
    if (i < NPAD) {
        g_deg[0][i] = 0; g_deg[1][i] = 0; g_deg[2][i] = 0;
    }
}

// ---------------- degree histogram ------------------------------------------------
__global__ void hist_kernel(const int* __restrict__ ei0, const int* __restrict__ ei1,
                            const int* __restrict__ ei2, int E) {
    int rel = blockIdx.y;
    const int* ei = (rel == 0) ? ei0 : (rel == 1) ? ei1 : ei2;
    int e = blockIdx.x * blockDim.x + threadIdx.x;
    if (e < E) atomicAdd(&g_deg[rel][ei[E + e]], 1);
}

// ---------------- exclusive scan (one block per relation, shfl-based) ------------
__global__ void scan_kernel(int n0, int n1, int n2) {
    int rel = blockIdx.x;
    int n = (rel == 0) ? n0 : (rel == 1) ? n1 : n2;
    __shared__ int shw[32];
    int t = threadIdx.x;
    int lane = t & 31;
    int wid = t >> 5;
    int running = 0;
    for (int base = 0; base < n; base += 1024) {
        int idx = base + t;
        int v = (idx < n) ? g_deg[rel][idx] : 0;
        int x = v;
#pragma unroll
        for (int off = 1; off < 32; off <<= 1) {
            int y = __shfl_up_sync(0xffffffffu, x, off);
            if (lane >= off) x += y;
        }
        if (lane == 31) shw[wid] = x;
        __syncthreads();
        if (wid == 0) {
            int s = shw[lane];
#pragma unroll
            for (int off = 1; off < 32; off <<= 1) {
                int y = __shfl_up_sync(0xffffffffu, s, off);
                if (lane >= off) s += y;
            }
            shw[lane] = s;
        }
        __syncthreads();
        int warpbase = (wid > 0) ? shw[wid - 1] : 0;
        int excl = running + warpbase + x - v;
        if (idx < n) {
            g_ofs[rel][idx] = excl;
            g_cur[rel][idx] = excl;
        }
        int total = shw[31];
        __syncthreads();
        running += total;
    }
    if (t == 0) g_ofs[rel][n] = running;
}

// ---------------- permute src ids into CSR order ---------------------------------
__global__ void permute_kernel(const int* __restrict__ ei0, const int* __restrict__ ei1,
                               const int* __restrict__ ei2, int E) {
    int rel = blockIdx.y;
    const int* ei = (rel == 0) ? ei0 : (rel == 1) ? ei1 : ei2;
    int e = blockIdx.x * blockDim.x + threadIdx.x;
    if (e < E) {
        int src = __ldg(ei + e);
        int dst = __ldg(ei + E + e);
        int pos = atomicAdd(&g_cur[rel][dst], 1);
        g_esrc[rel * MAX_E + pos] = src;
    }
}

// ---------------- atomic-free aggregation: mean over CSR neighborhoods -----------
// one warp per (rel, dst); 32 lanes x float4 = 128 floats; 4-way edge unroll
__global__ void aggregate_kernel(const float* __restrict__ x_user,
                                 const float* __restrict__ x_item,
                                 int n_user, int n_item) {
    int rel = blockIdx.y;
    int n = (rel == 0) ? n_item : n_user;
    const float* x = (rel == 1) ? x_item : x_user;
    float* mean = (rel == 0) ? g_mean_rates : (rel == 1) ? g_mean_rev : g_mean_fol;

    int w = (blockIdx.x * blockDim.x + threadIdx.x) >> 5;
    int lane = threadIdx.x & 31;
    if (w >= n) return;

    int start = g_ofs[rel][w];
    int end   = g_ofs[rel][w + 1];
    const int* esrc = g_esrc + rel * MAX_E;
    const size_t loff = (size_t)(lane * 4);

    float4 a0 = make_float4(0.f, 0.f, 0.f, 0.f);
    float4 a1 = make_float4(0.f, 0.f, 0.f, 0.f);
    float4 a2 = make_float4(0.f, 0.f, 0.f, 0.f);
    float4 a3 = make_float4(0.f, 0.f, 0.f, 0.f);
    int e = start;
    for (; e + 4 <= end; e += 4) {
        int s0 = __ldg(esrc + e);
        int s1 = __ldg(esrc + e + 1);
        int s2 = __ldg(esrc + e + 2);
        int s3 = __ldg(esrc + e + 3);
        float4 v0 = *(const float4*)(x + (size_t)s0 * D + loff);
        float4 v1 = *(const float4*)(x + (size_t)s1 * D + loff);
        float4 v2 = *(const float4*)(x + (size_t)s2 * D + loff);
        float4 v3 = *(const float4*)(x + (size_t)s3 * D + loff);
        a0.x += v0.x; a0.y += v0.y; a0.z += v0.z; a0.w += v0.w;
        a1.x += v1.x; a1.y += v1.y; a1.z += v1.z; a1.w += v1.w;
        a2.x += v2.x; a2.y += v2.y; a2.z += v2.z; a2.w += v2.w;
        a3.x += v3.x; a3.y += v3.y; a3.z += v3.z; a3.w += v3.w;
    }
    for (; e < end; e++) {
        int s0 = __ldg(esrc + e);
        float4 v0 = *(const float4*)(x + (size_t)s0 * D + loff);
        a0.x += v0.x; a0.y += v0.y; a0.z += v0.z; a0.w += v0.w;
    }
    int deg = end - start;
    float sc = (deg > 0) ? (1.0f / (float)deg) : 0.0f;
    float4 r;
    r.x = (a0.x + a1.x + a2.x + a3.x) * sc;
    r.y = (a0.y + a1.y + a2.y + a3.y) * sc;
    r.z = (a0.z + a1.z + a2.z + a3.z) * sc;
    r.w = (a0.w + a1.w + a2.w + a3.w) * sc;
    *(float4*)(mean + (size_t)w * D + loff) = r;
}

// ---------------- combined-weight prep -------------------------------------------
__global__ void build_user_wc(const float* __restrict__ Wl_rev, const float* __restrict__ bl_rev,
                              const float* __restrict__ Wr_rev,
                              const float* __restrict__ Wl_fol, const float* __restrict__ bl_fol,
                              const float* __restrict__ Wr_fol) {
    int t = blockIdx.x * blockDim.x + threadIdx.x;
    if (t < 384 * D) {
        int k = t >> 7, j = t & 127;
        float v;
        if (k < 128)       v = 0.5f * Wl_rev[j * D + k];
        else if (k < 256)  v = 0.5f * Wl_fol[j * D + (k - 128)];
        else               v = 0.5f * (Wr_rev[j * D + (k - 256)] + Wr_fol[j * D + (k - 256)]);
        g_wc_user[t] = v;
    }
    if (t < D) g_bias_user[t] = 0.5f * (bl_rev[t] + bl_fol[t]);
}

__global__ void build_item_wc(const float* __restrict__ Wl, const float* __restrict__ bl,
                              const float* __restrict__ Wr) {
    int t = blockIdx.x * blockDim.x + threadIdx.x;
    if (t < 256 * D) {
        int k = t >> 7, j = t & 127;
        float v = (k < 128) ? Wl[j * D + k] : Wr[j * D + (k - 128)];
        g_wc_item[t] = v;
    }
    if (t < D) g_bias_item[t] = bl[t];
}

// ---------------- fused dual-linear GEMM with packed f32x2 FMA -------------------
// gridDim.y: 0 = user ([mean_rev|mean_fol|x_u]@Wc_user), 1 = item ([mean_rates|x_i]@Wc_item)
// Inner product uses fma.rn.f32x2: acc pairs over adjacent j columns.
__global__ __launch_bounds__(256, 2)
void gemm_fused(const float* __restrict__ x_user, const float* __restrict__ x_item,
                float* __restrict__ out_user, float* __restrict__ out_item,
                int n_user, int n_item) {
    __shared__ float As[32][132];   // [k][row] transposed
    __shared__ float Bs[32][132];   // [k][j]

    const int mode = blockIdx.y;
    const int nrows   = (mode == 0) ? n_user : n_item;
    const int nchunks = (mode == 0) ? 3 : 2;
    const float* Wc   = (mode == 0) ? g_wc_user : g_wc_item;
    const float* bias = (mode == 0) ? g_bias_user : g_bias_item;
    float* out        = (mode == 0) ? out_user : out_item;

    const int tid = threadIdx.x;
    const int tx = tid & 15;
    const int ty = tid >> 4;
    const int row0 = blockIdx.x * 128;
    if (row0 >= nrows) return;

    // acc2[i][jp] = f32x2 pair of columns (ty*8 + 2*jp, ty*8 + 2*jp + 1), row tx*8+i
    unsigned long long acc2[8][4];
#pragma unroll
    for (int i = 0; i < 8; i++)
#pragma unroll
        for (int j = 0; j < 4; j++) acc2[i][j] = 0ull;

    for (int c = 0; c < nchunks; c++) {
        const float* A;
        if (mode == 0) {
            A = (c == 0) ? g_mean_rev : (c == 1) ? g_mean_fol : x_user;
        } else {
            A = (c == 0) ? g_mean_rates : x_item;
        }

#pragma unroll 1
        for (int ks = 0; ks < 4; ks++) {
            __syncthreads();
            // load A subtile (128 rows x 32 k), stored transposed
#pragma unroll
            for (int p = 0; p < 4; p++) {
                int r = p * 32 + (tid >> 3);
                int kk = (tid & 7) << 2;
                int grow = row0 + r;
                float4 v = make_float4(0.f, 0.f, 0.f, 0.f);
                if (grow < nrows)
                    v = *(const float4*)(A + (size_t)grow * D + (ks << 5) + kk);
                As[kk + 0][r] = v.x;
                As[kk + 1][r] = v.y;
                As[kk + 2][r] = v.z;
                As[kk + 3][r] = v.w;
            }
            // load B subtile (32 k x 128 j)
            {
                int k = tid >> 3;
                int j0 = (tid & 7) << 2;
                int kb = (c << 7) + (ks << 5) + k;
#pragma unroll
                for (int p = 0; p < 4; p++) {
                    float4 v = *(const float4*)(Wc + (size_t)kb * D + p * 32 + j0);
                    *(float4*)&Bs[k][p * 32 + j0] = v;
                }
            }
            __syncthreads();
            // 8x8 outer product via 8x4 packed f32x2 FMAs
#pragma unroll
            for (int k = 0; k < 32; k++) {
                float a[8];
                *(float4*)&a[0] = *(const float4*)&As[k][tx * 8];
                *(float4*)&a[4] = *(const float4*)&As[k][tx * 8 + 4];
                // b pairs: little-endian f32 pairs == f32x2 layout
                ulonglong2 bA = *(const ulonglong2*)&Bs[k][ty * 8];
                ulonglong2 bB = *(const ulonglong2*)&Bs[k][ty * 8 + 4];
                unsigned long long b2[4];
                b2[0] = bA.x; b2[1] = bA.y; b2[2] = bB.x; b2[3] = bB.y;
                // build all packed a-dups first (alu pipe), then issue FMA2 stream (fma pipe)
                unsigned long long a2[8];
#pragma unroll
                for (int i = 0; i < 8; i++)
                    asm("mov.b64 %0, {%1, %1};" : "=l"(a2[i]) : "f"(a[i]));
#pragma unroll
                for (int i = 0; i < 8; i++) {
#pragma unroll
                    for (int j = 0; j < 4; j++) {
                        asm("fma.rn.f32x2 %0, %1, %2, %0;"
                            : "+l"(acc2[i][j]) : "l"(a2[i]), "l"(b2[j]));
                    }
                }
            }
        }
    }

    // epilogue: unpack pairs, + bias, write out
    float bv[8];
    *(float4*)&bv[0] = *(const float4*)&bias[ty * 8];
    *(float4*)&bv[4] = *(const float4*)&bias[ty * 8 + 4];
#pragma unroll
    for (int i = 0; i < 8; i++) {
        int r = row0 + tx * 8 + i;
        if (r < nrows) {
            float o[8];
#pragma unroll
            for (int j = 0; j < 4; j++) {
                float lo, hi;
                asm("mov.b64 {%0, %1}, %2;" : "=f"(lo), "=f"(hi) : "l"(acc2[i][j]));
                o[2 * j]     = lo + bv[2 * j];
                o[2 * j + 1] = hi + bv[2 * j + 1];
            }
            *(float4*)(out + (size_t)r * D + ty * 8)     = *(float4*)&o[0];
            *(float4*)(out + (size_t)r * D + ty * 8 + 4) = *(float4*)&o[4];
        }
    }
}

// ---------------- launch ---------------------------------------------------------
extern "C" void kernel_launch(void* const* d_in, const int* in_sizes, int n_in,
                              void* d_out, int out_size) {
    const float* x_user   = (const float*)d_in[0];
    const float* x_item   = (const float*)d_in[1];
    const int*   ei_rates = (const int*)d_in[2];
    const int*   ei_rev   = (const int*)d_in[3];
    const int*   ei_fol   = (const int*)d_in[4];
    const float* Wl_rates = (const float*)d_in[5];
    const float* bl_rates = (const float*)d_in[6];
    const float* Wr_rates = (const float*)d_in[7];
    const float* Wl_rev   = (const float*)d_in[8];
    const float* bl_rev   = (const float*)d_in[9];
    const float* Wr_rev   = (const float*)d_in[10];
    const float* Wl_fol   = (const float*)d_in[11];
    const float* bl_fol   = (const float*)d_in[12];
    const float* Wr_fol   = (const float*)d_in[13];

    const int n_user = in_sizes[0] / D;
    const int n_item = in_sizes[1] / D;
    const int E      = in_sizes[2] / 2;

    float* out_user = (float*)d_out;
    float* out_item = out_user + (size_t)n_user * D;

    // 1) zero degree counters + weight prep (tiny)
    zero_deg<<<(NPAD + 255) / 256, 256>>>();
    build_user_wc<<<(384 * D + 255) / 256, 256>>>(Wl_rev, bl_rev, Wr_rev,
                                                  Wl_fol, bl_fol, Wr_fol);
    build_item_wc<<<(256 * D + 255) / 256, 256>>>(Wl_rates, bl_rates, Wr_rates);

    // 2) CSR build: histogram -> scan -> permute
    {
        dim3 grid((E + 255) / 256, 3);
        hist_kernel<<<grid, 256>>>(ei_rates, ei_rev, ei_fol, E);
        scan_kernel<<<3, 1024>>>(n_item, n_user, n_user);
        permute_kernel<<<grid, 256>>>(ei_rates, ei_rev, ei_fol, E);
    }

    // 3) atomic-free aggregation (mean) for all 3 relations in one launch
    {
        int max_n = (n_user > n_item) ? n_user : n_item;
        dim3 grid((max_n + 7) / 8, 3);
        aggregate_kernel<<<grid, 256>>>(x_user, x_item, n_user, n_item);
    }

    // 4) fused GEMM + bias for both node types in one launch
    {
        int max_rows = (n_user > n_item) ? n_user : n_item;
        dim3 grid((max_rows + 127) / 128, 2);
        gemm_fused<<<grid, 256>>>(x_user, x_item, out_user, out_item, n_user, n_item);
    }
}

// round 11
// speedup vs baseline: 1.5982x; 1.2997x over previous
#include <cuda_runtime.h>
#include <cuda_bf16.h>
#include <math.h>
#include <stdint.h>

#define D 128
#define MAX_N 50000
#define MAX_E 600000
#define NPAD 50048

// ---------------- scratch (static device allocations; no runtime alloc) ---------
__device__ float g_mean_rates[MAX_N * D];   // dst = item
__device__ float g_mean_rev[MAX_N * D];     // dst = user
__device__ float g_mean_fol[MAX_N * D];     // dst = user
__device__ int   g_deg[3][NPAD];
__device__ int   g_ofs[3][NPAD + 1];
__device__ int   g_cur[3][NPAD];
__device__ int   g_esrc[3 * MAX_E];
// transposed combined weights, bf16 hi/lo split: [j][k]
__device__ __nv_bfloat16 g_wbt_user_hi[128 * 384];
__device__ __nv_bfloat16 g_wbt_user_lo[128 * 384];
__device__ __nv_bfloat16 g_wbt_item_hi[128 * 256];
__device__ __nv_bfloat16 g_wbt_item_lo[128 * 256];
__device__ float g_bias_user[D];
__device__ float g_bias_item[D];

// ---------------- helpers ---------------------------------------------------------
__device__ __forceinline__ uint32_t smem_u32(const void* p) {
    uint32_t a;
    asm("{ .reg .u64 t; cvta.to.shared.u64 t, %1; cvt.u32.u64 %0, t; }"
        : "=r"(a) : "l"(p));
    return a;
}
__device__ __forceinline__ void f2_to_hilo(float f0, float f1, uint32_t& hi, uint32_t& lo) {
    __nv_bfloat16 h0 = __float2bfloat16_rn(f0);
    __nv_bfloat16 h1 = __float2bfloat16_rn(f1);
    __nv_bfloat16 l0 = __float2bfloat16_rn(f0 - __bfloat162float(h0));
    __nv_bfloat16 l1 = __float2bfloat16_rn(f1 - __bfloat162float(h1));
    __nv_bfloat162 hp = __halves2bfloat162(h0, h1);
    __nv_bfloat162 lp = __halves2bfloat162(l0, l1);
    hi = *(uint32_t*)&hp;
    lo = *(uint32_t*)&lp;
}

#define LDM_X4(r0, r1, r2, r3, addr)                                              \
    asm volatile("ldmatrix.sync.aligned.m8n8.x4.shared.b16 {%0,%1,%2,%3}, [%4];"  \
                 : "=r"(r0), "=r"(r1), "=r"(r2), "=r"(r3) : "r"(addr))

#define MMA16816(c, a, b0, b1)                                                    \
    asm volatile("mma.sync.aligned.m16n8k16.row.col.f32.bf16.bf16.f32 "           \
                 "{%0,%1,%2,%3}, {%4,%5,%6,%7}, {%8,%9}, {%0,%1,%2,%3};"          \
                 : "+f"((c)[0]), "+f"((c)[1]), "+f"((c)[2]), "+f"((c)[3])         \
                 : "r"((a)[0]), "r"((a)[1]), "r"((a)[2]), "r"((a)[3]),            \
                   "r"(b0), "r"(b1))

#define STS128(addr, v0, v1, v2, v3)                                              \
    asm volatile("st.shared.v4.b32 [%0], {%1, %2, %3, %4};"                       \
                 :: "r"(addr), "r"(v0), "r"(v1), "r"(v2), "r"(v3) : "memory")

// ---------------- zero degree counters -------------------------------------------
__global__ void zero_deg() {
    int i = blockIdx.x * blockDim.x + threadIdx.x;
    if (i < NPAD) { g_deg[0][i] = 0; g_deg[1][i] = 0; g_deg[2][i] = 0; }
}

// ---------------- degree histogram ------------------------------------------------
__global__ void hist_kernel(const int* __restrict__ ei0, const int* __restrict__ ei1,
                            const int* __restrict__ ei2, int E) {
    int rel = blockIdx.y;
    const int* ei = (rel == 0) ? ei0 : (rel == 1) ? ei1 : ei2;
    int e = blockIdx.x * blockDim.x + threadIdx.x;
    if (e < E) atomicAdd(&g_deg[rel][ei[E + e]], 1);
}

// ---------------- exclusive scan (one block per relation) ------------------------
__global__ void scan_kernel(int n0, int n1, int n2) {
    int rel = blockIdx.x;
    int n = (rel == 0) ? n0 : (rel == 1) ? n1 : n2;
    __shared__ int shw[32];
    int t = threadIdx.x;
    int lane = t & 31;
    int wid = t >> 5;
    int running = 0;
    for (int base = 0; base < n; base += 1024) {
        int idx = base + t;
        int v = (idx < n) ? g_deg[rel][idx] : 0;
        int x = v;
#pragma unroll
        for (int off = 1; off < 32; off <<= 1) {
            int y = __shfl_up_sync(0xffffffffu, x, off);
            if (lane >= off) x += y;
        }
        if (lane == 31) shw[wid] = x;
        __syncthreads();
        if (wid == 0) {
            int s = shw[lane];
#pragma unroll
            for (int off = 1; off < 32; off <<= 1) {
                int y = __shfl_up_sync(0xffffffffu, s, off);
                if (lane >= off) s += y;
            }
            shw[lane] = s;
        }
        __syncthreads();
        int warpbase = (wid > 0) ? shw[wid - 1] : 0;
        int excl = running + warpbase + x - v;
        if (idx < n) {
            g_ofs[rel][idx] = excl;
            g_cur[rel][idx] = excl;
        }
        int total = shw[31];
        __syncthreads();
        running += total;
    }
    if (t == 0) g_ofs[rel][n] = running;
}

// ---------------- permute src ids into CSR order ---------------------------------
__global__ void permute_kernel(const int* __restrict__ ei0, const int* __restrict__ ei1,
                               const int* __restrict__ ei2, int E) {
    int rel = blockIdx.y;
    const int* ei = (rel == 0) ? ei0 : (rel == 1) ? ei1 : ei2;
    int e = blockIdx.x * blockDim.x + threadIdx.x;
    if (e < E) {
        int src = __ldg(ei + e);
        int dst = __ldg(ei + E + e);
        int pos = atomicAdd(&g_cur[rel][dst], 1);
        g_esrc[rel * MAX_E + pos] = src;
    }
}

// ---------------- atomic-free aggregation: mean over CSR neighborhoods -----------
__global__ void aggregate_kernel(const float* __restrict__ x_user,
                                 const float* __restrict__ x_item,
                                 int n_user, int n_item) {
    int rel = blockIdx.y;
    int n = (rel == 0) ? n_item : n_user;
    const float* x = (rel == 1) ? x_item : x_user;
    float* mean = (rel == 0) ? g_mean_rates : (rel == 1) ? g_mean_rev : g_mean_fol;

    int w = (blockIdx.x * blockDim.x + threadIdx.x) >> 5;
    int lane = threadIdx.x & 31;
    if (w >= n) return;

    int start = g_ofs[rel][w];
    int end   = g_ofs[rel][w + 1];
    const int* esrc = g_esrc + rel * MAX_E;
    const size_t loff = (size_t)(lane * 4);

    float4 a0 = make_float4(0.f, 0.f, 0.f, 0.f);
    float4 a1 = make_float4(0.f, 0.f, 0.f, 0.f);
    float4 a2 = make_float4(0.f, 0.f, 0.f, 0.f);
    float4 a3 = make_float4(0.f, 0.f, 0.f, 0.f);
    int e = start;
    for (; e + 4 <= end; e += 4) {
        int s0 = __ldg(esrc + e);
        int s1 = __ldg(esrc + e + 1);
        int s2 = __ldg(esrc + e + 2);
        int s3 = __ldg(esrc + e + 3);
        float4 v0 = *(const float4*)(x + (size_t)s0 * D + loff);
        float4 v1 = *(const float4*)(x + (size_t)s1 * D + loff);
        float4 v2 = *(const float4*)(x + (size_t)s2 * D + loff);
        float4 v3 = *(const float4*)(x + (size_t)s3 * D + loff);
        a0.x += v0.x; a0.y += v0.y; a0.z += v0.z; a0.w += v0.w;
        a1.x += v1.x; a1.y += v1.y; a1.z += v1.z; a1.w += v1.w;
        a2.x += v2.x; a2.y += v2.y; a2.z += v2.z; a2.w += v2.w;
        a3.x += v3.x; a3.y += v3.y; a3.z += v3.z; a3.w += v3.w;
    }
    for (; e < end; e++) {
        int s0 = __ldg(esrc + e);
        float4 v0 = *(const float4*)(x + (size_t)s0 * D + loff);
        a0.x += v0.x; a0.y += v0.y; a0.z += v0.z; a0.w += v0.w;
    }
    int deg = end - start;
    float sc = (deg > 0) ? (1.0f / (float)deg) : 0.0f;
    float4 r;
    r.x = (a0.x + a1.x + a2.x + a3.x) * sc;
    r.y = (a0.y + a1.y + a2.y + a3.y) * sc;
    r.z = (a0.z + a1.z + a2.z + a3.z) * sc;
    r.w = (a0.w + a1.w + a2.w + a3.w) * sc;
    *(float4*)(mean + (size_t)w * D + loff) = r;
}

// ---------------- combined-weight prep: transposed bf16 hi/lo --------------------
// user: K 0..127 = mean_rev (0.5*Wl_rev), 128..255 = mean_fol (0.5*Wl_fol),
//       256..383 = x_user (0.5*(Wr_rev + Wr_fol))
__global__ void build_user_wc(const float* __restrict__ Wl_rev, const float* __restrict__ bl_rev,
                              const float* __restrict__ Wr_rev,
                              const float* __restrict__ Wl_fol, const float* __restrict__ bl_fol,
                              const float* __restrict__ Wr_fol) {
    int t = blockIdx.x * blockDim.x + threadIdx.x;
    if (t < 384 * 128) {
        int k = t >> 7, j = t & 127;
        float v;
        if (k < 128)       v = 0.5f * Wl_rev[j * D + k];
        else if (k < 256)  v = 0.5f * Wl_fol[j * D + (k - 128)];
        else               v = 0.5f * (Wr_rev[j * D + (k - 256)] + Wr_fol[j * D + (k - 256)]);
        __nv_bfloat16 hi = __float2bfloat16_rn(v);
        __nv_bfloat16 lo = __float2bfloat16_rn(v - __bfloat162float(hi));
        g_wbt_user_hi[j * 384 + k] = hi;
        g_wbt_user_lo[j * 384 + k] = lo;
    }
    if (t < D) g_bias_user[t] = 0.5f * (bl_rev[t] + bl_fol[t]);
}

// item: K 0..127 = mean_rates (Wl_rates), 128..255 = x_item (Wr_rates)
__global__ void build_item_wc(const float* __restrict__ Wl, const float* __restrict__ bl,
                              const float* __restrict__ Wr) {
    int t = blockIdx.x * blockDim.x + threadIdx.x;
    if (t < 256 * 128) {
        int k = t >> 7, j = t & 127;
        float v = (k < 128) ? Wl[j * D + k] : Wr[j * D + (k - 128)];
        __nv_bfloat16 hi = __float2bfloat16_rn(v);
        __nv_bfloat16 lo = __float2bfloat16_rn(v - __bfloat162float(hi));
        g_wbt_item_hi[j * 256 + k] = hi;
        g_wbt_item_lo[j * 256 + k] = lo;
    }
    if (t < D) g_bias_item[t] = bl[t];
}

// ---------------- mma.sync bf16x3 GEMM -------------------------------------------
// 128x128 output tile per CTA, 256 thr = 8 warps (4 row-groups x 2 col-groups).
// K consumed in chunks of 64 fp32; A split to bf16 hi/lo on the fly; B pre-split.
// Smem tiles stride 144B (72 bf16) for conflict-free ldmatrix.
#define LDB 144
#define SA_HI 0
#define SA_LO 18432
#define SB_HI 36864
#define SB_LO 55296
#define SM_BIAS_OFF 73728
#define SM_TOT (73728 + 512)

__global__ __launch_bounds__(256, 2)
void gemm_mma(const float* __restrict__ x_user, const float* __restrict__ x_item,
              float* __restrict__ out_user, float* __restrict__ out_item,
              int n_user, int n_item) {
    extern __shared__ char smem[];
    uint32_t sb = smem_u32(smem);
    const int tid = threadIdx.x;
    const int lane = tid & 31;
    const int w = tid >> 5;
    const int wr = w & 3;          // row group: 32 rows
    const int wc = w >> 2;         // col group: 64 cols
    const int mode = blockIdx.y;   // 0 user, 1 item
    const int nrows = mode ? n_item : n_user;
    const int nch = mode ? 4 : 6;
    const int KS = mode ? 256 : 384;
    const __nv_bfloat16* wbh = mode ? g_wbt_item_hi : g_wbt_user_hi;
    const __nv_bfloat16* wbl = mode ? g_wbt_item_lo : g_wbt_user_lo;
    const float* bias = mode ? g_bias_item : g_bias_user;
    float* out = mode ? out_item : out_user;
    const int row0 = blockIdx.x * 128;
    if (row0 >= nrows) return;

    if (tid < 128) ((float*)(smem + SM_BIAS_OFF))[tid] = bias[tid];

    float acc[2][8][4];
#pragma unroll
    for (int i = 0; i < 2; i++)
#pragma unroll
        for (int j = 0; j < 8; j++)
#pragma unroll
            for (int q = 0; q < 4; q++) acc[i][j][q] = 0.f;

    const int r_st = tid >> 1;     // staging row 0..127
    const int half = tid & 1;      // 32-element half

    for (int c = 0; c < nch; c++) {
        const float* A;
        if (mode == 0) A = (c < 2) ? g_mean_rev : (c < 4) ? g_mean_fol : x_user;
        else           A = (c < 2) ? g_mean_rates : x_item;

        __syncthreads();   // previous chunk's ldmatrix reads complete

        // ---- stage A (128 x 64 fp32 -> hi/lo bf16) ----
        {
            int gr = row0 + r_st;
            bool ok = (gr < nrows);
            const float4* src = (const float4*)(A + (size_t)gr * D + (c & 1) * 64 + half * 32);
            uint32_t abase = sb + (uint32_t)(r_st * LDB + half * 64);
#pragma unroll
            for (int q = 0; q < 4; q++) {
                float4 va = ok ? __ldg(src + 2 * q)     : make_float4(0.f, 0.f, 0.f, 0.f);
                float4 vb = ok ? __ldg(src + 2 * q + 1) : make_float4(0.f, 0.f, 0.f, 0.f);
                uint32_t h[4], l[4];
                f2_to_hilo(va.x, va.y, h[0], l[0]);
                f2_to_hilo(va.z, va.w, h[1], l[1]);
                f2_to_hilo(vb.x, vb.y, h[2], l[2]);
                f2_to_hilo(vb.z, vb.w, h[3], l[3]);
                STS128(abase + SA_HI + q * 16, h[0], h[1], h[2], h[3]);
                STS128(abase + SA_LO + q * 16, l[0], l[1], l[2], l[3]);
            }
        }
        // ---- stage B (128 j x 64 k bf16, hi/lo) ----
        {
            const uint4* bh = (const uint4*)(wbh + (size_t)r_st * KS + c * 64 + half * 32);
            const uint4* bl = (const uint4*)(wbl + (size_t)r_st * KS + c * 64 + half * 32);
            uint32_t bbase = sb + (uint32_t)(r_st * LDB + half * 64);
#pragma unroll
            for (int q = 0; q < 4; q++) {
                uint4 vh = __ldg(bh + q);
                uint4 vl = __ldg(bl + q);
                STS128(bbase + SB_HI + q * 16, vh.x, vh.y, vh.z, vh.w);
                STS128(bbase + SB_LO + q * 16, vl.x, vl.y, vl.z, vl.w);
            }
        }
        __syncthreads();

        // ---- compute: 4 k16 steps ----
#pragma unroll
        for (int ks = 0; ks < 4; ks++) {
            uint32_t cb = (uint32_t)(ks * 32 + (lane >> 4) * 16);
            uint32_t ar = (uint32_t)((wr * 32 + (lane & 15)) * LDB);
            uint32_t ah[2][4], al[2][4];
            LDM_X4(ah[0][0], ah[0][1], ah[0][2], ah[0][3], sb + SA_HI + ar + cb);
            LDM_X4(ah[1][0], ah[1][1], ah[1][2], ah[1][3], sb + SA_HI + ar + 16 * LDB + cb);
            LDM_X4(al[0][0], al[0][1], al[0][2], al[0][3], sb + SA_LO + ar + cb);
            LDM_X4(al[1][0], al[1][1], al[1][2], al[1][3], sb + SA_LO + ar + 16 * LDB + cb);
#pragma unroll
            for (int ng = 0; ng < 4; ng++) {
                uint32_t br = (uint32_t)((wc * 64 + ng * 16 + (lane & 15)) * LDB);
                uint32_t bh0, bh1, bh2, bh3, bl0, bl1, bl2, bl3;
                LDM_X4(bh0, bh1, bh2, bh3, sb + SB_HI + br + cb);
                LDM_X4(bl0, bl1, bl2, bl3, sb + SB_LO + br + cb);
#pragma unroll
                for (int mt = 0; mt < 2; mt++) {
                    MMA16816(acc[mt][2 * ng],     ah[mt], bh0, bh2);
                    MMA16816(acc[mt][2 * ng],     al[mt], bh0, bh2);
                    MMA16816(acc[mt][2 * ng],     ah[mt], bl0, bl2);
                    MMA16816(acc[mt][2 * ng + 1], ah[mt], bh1, bh3);
                    MMA16816(acc[mt][2 * ng + 1], al[mt], bh1, bh3);
                    MMA16816(acc[mt][2 * ng + 1], ah[mt], bl1, bl3);
                }
            }
        }
    }

    // ---- epilogue: acc + bias -> out ----
    const float* bs = (const float*)(smem + SM_BIAS_OFF);
#pragma unroll
    for (int mt = 0; mt < 2; mt++) {
        int r0g = row0 + wr * 32 + mt * 16 + (lane >> 2);
        int r1g = r0g + 8;
#pragma unroll
        for (int nt = 0; nt < 8; nt++) {
            int j = wc * 64 + nt * 8 + (lane & 3) * 2;
            float b0 = bs[j], b1 = bs[j + 1];
            if (r0g < nrows) {
                float2 o = make_float2(acc[mt][nt][0] + b0, acc[mt][nt][1] + b1);
                *(float2*)(out + (size_t)r0g * D + j) = o;
            }
            if (r1g < nrows) {
                float2 o = make_float2(acc[mt][nt][2] + b0, acc[mt][nt][3] + b1);
                *(float2*)(out + (size_t)r1g * D + j) = o;
            }
        }
    }
}

// ---------------- launch ---------------------------------------------------------
extern "C" void kernel_launch(void* const* d_in, const int* in_sizes, int n_in,
                              void* d_out, int out_size) {
    const float* x_user   = (const float*)d_in[0];
    const float* x_item   = (const float*)d_in[1];
    const int*   ei_rates = (const int*)d_in[2];
    const int*   ei_rev   = (const int*)d_in[3];
    const int*   ei_fol   = (const int*)d_in[4];
    const float* Wl_rates = (const float*)d_in[5];
    const float* bl_rates = (const float*)d_in[6];
    const float* Wr_rates = (const float*)d_in[7];
    const float* Wl_rev   = (const float*)d_in[8];
    const float* bl_rev   = (const float*)d_in[9];
    const float* Wr_rev   = (const float*)d_in[10];
    const float* Wl_fol   = (const float*)d_in[11];
    const float* bl_fol   = (const float*)d_in[12];
    const float* Wr_fol   = (const float*)d_in[13];

    const int n_user = in_sizes[0] / D;
    const int n_item = in_sizes[1] / D;
    const int E      = in_sizes[2] / 2;

    float* out_user = (float*)d_out;
    float* out_item = out_user + (size_t)n_user * D;

    // opt-in to >48KB dynamic smem (host attribute, not an allocation)
    cudaFuncSetAttribute(gemm_mma, cudaFuncAttributeMaxDynamicSharedMemorySize, SM_TOT);

    // 1) zero degree counters + weight prep (tiny)
    zero_deg<<<(NPAD + 255) / 256, 256>>>();
    build_user_wc<<<(384 * 128 + 255) / 256, 256>>>(Wl_rev, bl_rev, Wr_rev,
                                                    Wl_fol, bl_fol, Wr_fol);
    build_item_wc<<<(256 * 128 + 255) / 256, 256>>>(Wl_rates, bl_rates, Wr_rates);

    // 2) CSR build: histogram -> scan -> permute
    {
        dim3 grid((E + 255) / 256, 3);
        hist_kernel<<<grid, 256>>>(ei_rates, ei_rev, ei_fol, E);
        scan_kernel<<<3, 1024>>>(n_item, n_user, n_user);
        permute_kernel<<<grid, 256>>>(ei_rates, ei_rev, ei_fol, E);
    }

    // 3) atomic-free aggregation (mean) for all 3 relations in one launch
    {
        int max_n = (n_user > n_item) ? n_user : n_item;
        dim3 grid((max_n + 7) / 8, 3);
        aggregate_kernel<<<grid, 256>>>(x_user, x_item, n_user, n_item);
    }

    // 4) mma.sync bf16x3 GEMM + bias for both node types in one launch
    {
        int max_rows = (n_user > n_item) ? n_user : n_item;
        dim3 grid((max_rows + 127) / 128, 2);
        gemm_mma<<<grid, 256, SM_TOT>>>(x_user, x_item, out_user, out_item,
                                        n_user, n_item);
    }
}